// round 10
// baseline (speedup 1.0000x reference)
#include <cuda_runtime.h>
#include <math.h>
#include <limits.h>

#define NRR   4096
#define NLL   16384
#define KM    8
#define TK    10
#define CF    16
#define NB    4
#define CDX   3
#define CDY   11
#define CDZ   11
#define NCELL (CDX*CDY*CDZ)      // 363
#define NCB   (NB*NCELL)         // 1452
#define CAPW  512
#define WPB   8                  // warps per block
#define RPW   2                  // radars per warp
#define GRD   (NRR/(WPB*RPW))    // 256 blocks
#define KNONE 0xFFFFFFFFu
#define F_LOG2PI 1.8378770664093453f

// ---------------- device scratch ----------------
__device__ int            g_ccnt[NCB];
__device__ int            g_cstart[NCB + 1];
__device__ int            g_ccur[NCB];
__device__ int            g_cpos[NLL];
__device__ unsigned short g_cidx[NLL];
__device__ int            g_fb[NB * TK];
__device__ float4         g_part[NRR];
__device__ int            g_bar_cnt;       // zero-init, self-resetting
__device__ int            g_bar_gen;       // monotonically increasing across replays

__device__ __forceinline__ float softplusf(float x) {
    return log1pf(expf(-fabsf(x))) + fmaxf(x, 0.0f);
}
__device__ __forceinline__ int cell_of(int b, int c1, int c2, int c3) {
    return b * NCELL + (((c1 >> 4) * CDY + (c2 >> 4)) * CDZ + (c3 >> 4));
}

// grid-wide barrier: all 256 blocks are co-resident by construction
__device__ __forceinline__ void gsync() {
    __threadfence();
    __syncthreads();
    if (threadIdx.x == 0) {
        int gen = *(volatile int*)&g_bar_gen;
        if (atomicAdd(&g_bar_cnt, 1) == (int)gridDim.x - 1) {
            g_bar_cnt = 0;
            __threadfence();
            *(volatile int*)&g_bar_gen = gen + 1;
        } else {
            while (*(volatile int*)&g_bar_gen == gen) {}
        }
        __threadfence();
    }
    __syncthreads();
}

// ---------------- single fused kernel ----------------
__global__ __launch_bounds__(256) void k_all(
    const float* __restrict__ mu_off,  const float* __restrict__ log_sig_off,
    const float* __restrict__ mu_int,  const float* __restrict__ occ_logit,
    const float* __restrict__ mix_logit, const float* __restrict__ lfeat,
    const int* __restrict__ ridx, const int* __restrict__ lidx,
    float* __restrict__ out)
{
    __shared__ unsigned s_buf[WPB][CAPW];
    __shared__ float    s_cmp[WPB][KM][9];
    __shared__ double   s_red[256][4];
    __shared__ int      s_scan[256];

    const int tid = threadIdx.x, lane = tid & 31, wid = tid >> 5;
    const int bid = blockIdx.x;
    const int gid = bid * 256 + tid;

    // ---- P0: zero cell counts; compute -inf tie fillers ----
    if (gid < NCB) g_ccnt[gid] = 0;
    if (bid == 1 && tid < NB) {              // block 1: fb (block 0 busy later)
        int c = 0;
        for (int j = 0; j < NLL && c < TK; ++j)
            if (lidx[j * 4] != tid) g_fb[tid * TK + c++] = j;
    }
    gsync();

    // ---- P1: count points per cell ----
    if (gid < NLL) {
        const int4 v = reinterpret_cast<const int4*>(lidx)[gid];
        atomicAdd(&g_ccnt[cell_of(v.x, v.y, v.z, v.w)], 1);
    }
    gsync();

    // ---- P2: block 0 exclusive scan over 1452 cells ----
    if (bid == 0) {
        const int base = tid * 6;
        int c[6], s = 0;
        #pragma unroll
        for (int q = 0; q < 6; ++q) {
            c[q] = (base + q < NCB) ? g_ccnt[base + q] : 0;
            s += c[q];
        }
        s_scan[tid] = s;
        __syncthreads();
        for (int d = 1; d < 256; d <<= 1) {
            int v = (tid >= d) ? s_scan[tid - d] : 0;
            __syncthreads();
            s_scan[tid] += v;
            __syncthreads();
        }
        int e = s_scan[tid] - s;
        #pragma unroll
        for (int q = 0; q < 6; ++q) {
            if (base + q < NCB) { g_cstart[base + q] = e; g_ccur[base + q] = e; }
            e += c[q];
        }
        if (tid == 255) g_cstart[NCB] = s_scan[255];
    }
    gsync();

    // ---- P3: scatter (cell-sorted packed pos + original index) ----
    if (gid < NLL) {
        const int4 v = reinterpret_cast<const int4*>(lidx)[gid];
        int pos = atomicAdd(&g_ccur[cell_of(v.x, v.y, v.z, v.w)], 1);
        g_cpos[pos] = (v.y << 16) | (v.z << 8) | v.w;
        g_cidx[pos] = (unsigned short)gid;
    }
    gsync();

    // ---- P4: per-radar grid-accelerated top-10 + MDN (2 radars per warp) ----
    #pragma unroll 1
    for (int rr = 0; rr < RPW; ++rr) {
        const int i = (bid * WPB + wid) * RPW + rr;
        const int4 r = reinterpret_cast<const int4*>(ridx)[i];
        const int b = r.x, r1 = r.y, r2 = r.z, r3 = r.w;
        const int cx = r1 >> 4, cy = r2 >> 4, cz = r3 >> 4;
        const int bbeg = g_cstart[b * NCELL];
        const int bend = g_cstart[(b + 1) * NCELL];
        const int nbL  = bend - bbeg;

        int cnt = 0;
        #pragma unroll 1
        for (int R = 1;; ++R) {
            const int x0 = max(cx - R, 0), x1 = min(cx + R, CDX - 1);
            const int y0 = max(cy - R, 0), y1 = min(cy + R, CDY - 1);
            const int z0 = max(cz - R, 0), z1 = min(cz + R, CDZ - 1);
            int g = INT_MAX;
            if (x0 > 0)       g = min(g, r1 - x0 * 16);
            if (x1 < CDX - 1) g = min(g, (x1 + 1) * 16 - r1);
            if (y0 > 0)       g = min(g, r2 - y0 * 16);
            if (y1 < CDY - 1) g = min(g, (y1 + 1) * 16 - r2);
            if (z0 > 0)       g = min(g, r3 - z0 * 16);
            if (z1 < CDZ - 1) g = min(g, (z1 + 1) * 16 - r3);
            const bool whole = (g == INT_MAX);
            const unsigned g2 = whole ? 0x7FFFFFFFu : (unsigned)(g * g);

            cnt = 0;
            #pragma unroll 1
            for (int xx = x0; xx <= x1; ++xx) {
                #pragma unroll 1
                for (int yy = y0; yy <= y1; ++yy) {
                    const int crow = b * NCELL + ((xx * CDY + yy) * CDZ);
                    const int beg = g_cstart[crow + z0];
                    const int end = g_cstart[crow + z1 + 1];
                    for (int j0 = beg; j0 < end; j0 += 32) {
                        const int j = j0 + lane;
                        bool pred = false; unsigned key = 0;
                        if (j < end) {
                            const int p = g_cpos[j];
                            int d3 = (p & 255) - r3;
                            int d2 = ((p >> 8) & 255) - r2;
                            int d1 = (p >> 16) - r1;
                            unsigned dd = (unsigned)(d1 * d1 + d2 * d2 + d3 * d3);
                            if (dd < g2) { pred = true; key = (dd << 16) | g_cidx[j]; }
                        }
                        unsigned m = __ballot_sync(0xFFFFFFFFu, pred);
                        if (pred) {
                            int off = cnt + __popc(m & ((1u << lane) - 1u));
                            if (off < CAPW) s_buf[wid][off] = key;
                        }
                        cnt += __popc(m);
                    }
                }
            }
            if (cnt >= TK || whole) break;
        }

        // exact top-10 extraction
        unsigned mykey = KNONE;
        long long last = -1;
        if (cnt <= CAPW) {
            #pragma unroll
            for (int t = 0; t < TK; ++t) {
                unsigned best = KNONE;
                for (int q = lane; q < cnt; q += 32) {
                    unsigned v = s_buf[wid][q];
                    if ((long long)v > last && v < best) best = v;
                }
                #pragma unroll
                for (int d = 16; d; d >>= 1)
                    best = min(best, __shfl_xor_sync(0xFFFFFFFFu, best, d));
                if (lane == t) mykey = best;
                last = (long long)best;
            }
        } else {
            // overflow fallback: exact extraction over whole batch
            #pragma unroll 1
            for (int t = 0; t < TK; ++t) {
                unsigned best = KNONE;
                for (int q = bbeg + lane; q < bend; q += 32) {
                    const int p = g_cpos[q];
                    int d3 = (p & 255) - r3;
                    int d2 = ((p >> 8) & 255) - r2;
                    int d1 = (p >> 16) - r1;
                    unsigned dd = (unsigned)(d1 * d1 + d2 * d2 + d3 * d3);
                    unsigned v = (dd << 16) | g_cidx[q];
                    if ((long long)v > last && v < best) best = v;
                }
                #pragma unroll
                for (int d = 16; d; d >>= 1)
                    best = min(best, __shfl_xor_sync(0xFFFFFFFFu, best, d));
                if (lane == t) mykey = best;
                last = (long long)best;
            }
        }

        // per-component precompute (lanes 0..7)
        const int k = lane;
        float v = (k < KM) ? mix_logit[i * KM + k] : -INFINITY;
        float mx = v;
        #pragma unroll
        for (int d = 16; d; d >>= 1) mx = fmaxf(mx, __shfl_xor_sync(0xFFFFFFFFu, mx, d));
        float ex = (k < KM) ? expf(v - mx) : 0.0f;
        float sm = ex;
        #pragma unroll
        for (int d = 16; d; d >>= 1) sm += __shfl_xor_sync(0xFFFFFFFFu, sm, d);
        float lz = mx + logf(sm);

        float o = (k < KM) ? occ_logit[i * KM + k] : -INFINITY;
        #pragma unroll
        for (int d = 16; d; d >>= 1) o = fmaxf(o, __shfl_xor_sync(0xFFFFFFFFu, o, d));
        const float occ_any = o;

        if (k < KM) {
            const int bk = (i * KM + k) * 3;
            float l0 = log_sig_off[bk], l1 = log_sig_off[bk + 1], l2 = log_sig_off[bk + 2];
            s_cmp[wid][k][0] = v - lz;
            s_cmp[wid][k][1] = mu_off[bk];
            s_cmp[wid][k][2] = mu_off[bk + 1];
            s_cmp[wid][k][3] = mu_off[bk + 2];
            s_cmp[wid][k][4] = 1.0f / (expf(2.0f * l0) + 1e-12f);
            s_cmp[wid][k][5] = 1.0f / (expf(2.0f * l1) + 1e-12f);
            s_cmp[wid][k][6] = 1.0f / (expf(2.0f * l2) + 1e-12f);
            s_cmp[wid][k][7] = 2.0f * (l0 + l1 + l2) + 3.0f * F_LOG2PI;
            s_cmp[wid][k][8] = mu_int[i * KM + k];
        }
        __syncwarp();

        // per-slot MDN + intensity (lanes 0..9)
        const bool matched = nbL > 0;
        unsigned rm = __ballot_sync(0xFFFFFFFFu, mykey != KNONE && lane < TK);
        const int nvalid = __popc(rm);
        float SL = 0.0f, SI = 0.0f;
        if (lane < TK) {
            int j = (mykey != KNONE) ? (int)(mykey & 0xFFFFu)
                                     : g_fb[b * TK + (lane - nvalid)];
            const int4 lv = reinterpret_cast<const int4*>(lidx)[j];
            float y0 = matched ? (float)(lv.w - r3) : 0.0f;
            float y1 = matched ? (float)(lv.z - r2) : 0.0f;
            float y2 = matched ? (float)(lv.y - r1) : 0.0f;
            const float* f = lfeat + j * CF;
            float gi = matched ? 0.25f * (f[3] + f[7] + f[11] + f[15]) : 0.0f;

            float lp[KM]; float pm = -INFINITY;
            #pragma unroll
            for (int kk = 0; kk < KM; ++kk) {
                float d0 = y0 - s_cmp[wid][kk][1];
                float d1 = y1 - s_cmp[wid][kk][2];
                float d2 = y2 - s_cmp[wid][kk][3];
                float qv = d0 * d0 * s_cmp[wid][kk][4] + d1 * d1 * s_cmp[wid][kk][5]
                         + d2 * d2 * s_cmp[wid][kk][6];
                lp[kk] = -0.5f * (qv + s_cmp[wid][kk][7]) + s_cmp[wid][kk][0];
                pm = fmaxf(pm, lp[kk]);
            }
            float se = 0.0f;
            #pragma unroll
            for (int kk = 0; kk < KM; ++kk) se += expf(lp[kk] - pm);
            float logp = pm + logf(se);
            SL = logp;
            float ai = 0.0f;
            #pragma unroll
            for (int kk = 0; kk < KM; ++kk)
                ai += expf(lp[kk] - logp) * fabsf(s_cmp[wid][kk][8] - gi);
            SI = ai;
        }
        #pragma unroll
        for (int d = 16; d; d >>= 1) {
            SL += __shfl_xor_sync(0xFFFFFFFFu, SL, d);
            SI += __shfl_xor_sync(0xFFFFFFFFu, SI, d);
        }
        if (lane == 0) {
            float tgt = matched ? 1.0f : 0.0f;
            float occ = tgt * softplusf(-occ_any) + (1.0f - tgt) * softplusf(occ_any);
            g_part[i] = make_float4(occ, tgt, tgt * SL, tgt * SI);
        }
    }
    gsync();

    // ---- P5: block 0 deterministic double-precision reduction ----
    if (bid == 0) {
        double a0 = 0, a1 = 0, a2 = 0, a3 = 0;
        for (int q = tid; q < NRR; q += 256) {
            float4 p = g_part[q];
            a0 += p.x; a1 += p.y; a2 += p.z; a3 += p.w;
        }
        s_red[tid][0] = a0; s_red[tid][1] = a1; s_red[tid][2] = a2; s_red[tid][3] = a3;
        __syncthreads();
        for (int s = 128; s; s >>= 1) {
            if (tid < s) {
                s_red[tid][0] += s_red[tid + s][0];
                s_red[tid][1] += s_red[tid + s][1];
                s_red[tid][2] += s_red[tid + s][2];
                s_red[tid][3] += s_red[tid + s][3];
            }
            __syncthreads();
        }
        if (tid == 0) {
            double occ_loss = s_red[0][0] / (double)NRR;
            double cntm     = s_red[0][1];
            double mdn_nll  = -s_red[0][2] / (cntm * (double)TK);
            double int_loss =  s_red[0][3] / (cntm * (double)TK * (double)KM);
            out[0] = (float)(0.2 * occ_loss + 1.0 * mdn_nll + 0.1 * int_loss);
        }
    }
}

// ---------------- launch ----------------
extern "C" void kernel_launch(void* const* d_in, const int* in_sizes, int n_in,
                              void* d_out, int out_size) {
    const float* mu_off      = (const float*)d_in[0];
    const float* log_sig_off = (const float*)d_in[1];
    const float* mu_int      = (const float*)d_in[2];
    const float* occ_logit   = (const float*)d_in[3];
    const float* mix_logit   = (const float*)d_in[4];
    const float* lfeat       = (const float*)d_in[5];
    const int*   ridx        = (const int*)d_in[6];
    const int*   lidx        = (const int*)d_in[7];
    (void)in_sizes; (void)n_in; (void)out_size;

    k_all<<<GRD, 256>>>(mu_off, log_sig_off, mu_int, occ_logit, mix_logit,
                        lfeat, ridx, lidx, (float*)d_out);
}